// round 2
// baseline (speedup 1.0000x reference)
#include <cuda_runtime.h>
#include <mma.h>
#include <cstddef>

using namespace nvcuda;

#define SDIM 2048
#define BATCH 8

// Scratch for the softmax(P) matrix: 8 * 2048 * 2048 fp32 = 134 MB.
// __device__ global (module-load allocated) — allowed by the harness rules.
__device__ float g_P[(size_t)BATCH * SDIM * SDIM];

// Round fp32 -> tf32 value (kept in an f32 register, low mantissa bits zeroed).
__device__ __forceinline__ float to_tf32(float x) {
    float r;
    asm("cvt.rna.tf32.f32 %0, %1;" : "=f"(r) : "f"(x));
    return r;
}

// ---------------------------------------------------------------------------
// GEMM 1: P = Q @ K^T  (NT), 2-split tf32 for near-fp32 logit accuracy.
// grid (S/128, S/128, B), 256 threads.
// ---------------------------------------------------------------------------
__global__ __launch_bounds__(256, 1)
void gemm_qkT_split(const float* __restrict__ Q, const float* __restrict__ K) {
    __shared__ __align__(16) float Ah[128][20];
    __shared__ __align__(16) float Al[128][20];
    __shared__ __align__(16) float Bh[128][20];
    __shared__ __align__(16) float Bl[128][20];

    const int b = blockIdx.z;
    const float* Qb = Q + (size_t)b * SDIM * SDIM + (size_t)blockIdx.y * 128 * SDIM;
    const float* Kb = K + (size_t)b * SDIM * SDIM + (size_t)blockIdx.x * 128 * SDIM;
    float* Cb = g_P + (size_t)b * SDIM * SDIM + (size_t)blockIdx.y * 128 * SDIM
                    + (size_t)blockIdx.x * 128;

    const int tid  = threadIdx.x;
    const int warp = tid >> 5;
    const int wm   = warp >> 1;   // 0..3  (rows of 32)
    const int wn   = warp & 1;    // 0..1  (cols of 64)

    wmma::fragment<wmma::accumulator, 16, 16, 8, float> acc[2][4];
    #pragma unroll
    for (int i = 0; i < 2; i++)
        #pragma unroll
        for (int j = 0; j < 4; j++)
            wmma::fill_fragment(acc[i][j], 0.0f);

    for (int k0 = 0; k0 < SDIM; k0 += 16) {
        // Stage 128x16 tiles of Q and K; compute hi/lo tf32 split on the fly.
        #pragma unroll
        for (int i = 0; i < 2; i++) {
            int idx = tid + i * 256;          // 0..511
            int row = idx >> 2;               // 0..127
            int c   = (idx & 3) << 2;         // 0,4,8,12
            float4 q = *(const float4*)(Qb + (size_t)row * SDIM + k0 + c);
            float4 k = *(const float4*)(Kb + (size_t)row * SDIM + k0 + c);
            float h;
            h = to_tf32(q.x); Ah[row][c+0] = h; Al[row][c+0] = to_tf32(q.x - h);
            h = to_tf32(q.y); Ah[row][c+1] = h; Al[row][c+1] = to_tf32(q.y - h);
            h = to_tf32(q.z); Ah[row][c+2] = h; Al[row][c+2] = to_tf32(q.z - h);
            h = to_tf32(q.w); Ah[row][c+3] = h; Al[row][c+3] = to_tf32(q.w - h);
            h = to_tf32(k.x); Bh[row][c+0] = h; Bl[row][c+0] = to_tf32(k.x - h);
            h = to_tf32(k.y); Bh[row][c+1] = h; Bl[row][c+1] = to_tf32(k.y - h);
            h = to_tf32(k.z); Bh[row][c+2] = h; Bl[row][c+2] = to_tf32(k.z - h);
            h = to_tf32(k.w); Bh[row][c+3] = h; Bl[row][c+3] = to_tf32(k.w - h);
        }
        __syncthreads();

        #pragma unroll
        for (int ks = 0; ks < 16; ks += 8) {
            wmma::fragment<wmma::matrix_a, 16, 16, 8, wmma::precision::tf32, wmma::row_major> ah[2], al[2];
            wmma::fragment<wmma::matrix_b, 16, 16, 8, wmma::precision::tf32, wmma::col_major> bh[4], bl[4];
            #pragma unroll
            for (int i = 0; i < 2; i++) {
                wmma::load_matrix_sync(ah[i], &Ah[wm * 32 + i * 16][ks], 20);
                wmma::load_matrix_sync(al[i], &Al[wm * 32 + i * 16][ks], 20);
            }
            #pragma unroll
            for (int j = 0; j < 4; j++) {
                wmma::load_matrix_sync(bh[j], &Bh[wn * 64 + j * 16][ks], 20);
                wmma::load_matrix_sync(bl[j], &Bl[wn * 64 + j * 16][ks], 20);
            }
            #pragma unroll
            for (int i = 0; i < 2; i++)
                #pragma unroll
                for (int j = 0; j < 4; j++) {
                    wmma::mma_sync(acc[i][j], ah[i], bh[j], acc[i][j]);
                    wmma::mma_sync(acc[i][j], ah[i], bl[j], acc[i][j]);
                    wmma::mma_sync(acc[i][j], al[i], bh[j], acc[i][j]);
                }
        }
        __syncthreads();
    }

    #pragma unroll
    for (int i = 0; i < 2; i++)
        #pragma unroll
        for (int j = 0; j < 4; j++)
            wmma::store_matrix_sync(
                Cb + (size_t)(wm * 32 + i * 16) * SDIM + wn * 64 + j * 16,
                acc[i][j], SDIM, wmma::mem_row_major);
}

// ---------------------------------------------------------------------------
// Softmax over last dim, in place on g_P. One block per row, row in registers.
// ---------------------------------------------------------------------------
__global__ __launch_bounds__(256)
void softmax_rows() {
    __shared__ float red[8];
    float* p = g_P + (size_t)blockIdx.x * SDIM;
    const int tid  = threadIdx.x;
    const int lane = tid & 31;
    const int warp = tid >> 5;

    float4 a = *(const float4*)(p + tid * 4);
    float4 b = *(const float4*)(p + 1024 + tid * 4);

    float m = fmaxf(fmaxf(fmaxf(a.x, a.y), fmaxf(a.z, a.w)),
                    fmaxf(fmaxf(b.x, b.y), fmaxf(b.z, b.w)));
    #pragma unroll
    for (int o = 16; o > 0; o >>= 1)
        m = fmaxf(m, __shfl_xor_sync(0xffffffffu, m, o));
    if (lane == 0) red[warp] = m;
    __syncthreads();
    m = red[0];
    #pragma unroll
    for (int i = 1; i < 8; i++) m = fmaxf(m, red[i]);
    __syncthreads();   // red[] is reused for the sum below

    a.x = expf(a.x - m); a.y = expf(a.y - m); a.z = expf(a.z - m); a.w = expf(a.w - m);
    b.x = expf(b.x - m); b.y = expf(b.y - m); b.z = expf(b.z - m); b.w = expf(b.w - m);

    float s = (a.x + a.y) + (a.z + a.w) + (b.x + b.y) + (b.z + b.w);
    #pragma unroll
    for (int o = 16; o > 0; o >>= 1)
        s += __shfl_xor_sync(0xffffffffu, s, o);
    if (lane == 0) red[warp] = s;
    __syncthreads();
    s = red[0] + red[1] + red[2] + red[3] + red[4] + red[5] + red[6] + red[7];

    const float r = 1.0f / s;
    a.x *= r; a.y *= r; a.z *= r; a.w *= r;
    b.x *= r; b.y *= r; b.z *= r; b.w *= r;
    *(float4*)(p + tid * 4)        = a;
    *(float4*)(p + 1024 + tid * 4) = b;
}

// ---------------------------------------------------------------------------
// GEMM 2: out = V @ P  (NN), single tf32 (post-softmax, no exp amplification).
// grid (S/128, S/128, B), 256 threads.
// ---------------------------------------------------------------------------
__global__ __launch_bounds__(256, 1)
void gemm_vp(const float* __restrict__ V, float* __restrict__ O) {
    __shared__ __align__(16) float As[128][20];   // V tile [m][k]
    __shared__ __align__(16) float Bs[16][132];   // P tile [k][n]

    const int b = blockIdx.z;
    const float* Vb = V + (size_t)b * SDIM * SDIM + (size_t)blockIdx.y * 128 * SDIM;
    const float* Pb = g_P + (size_t)b * SDIM * SDIM;
    float* Ob = O + (size_t)b * SDIM * SDIM + (size_t)blockIdx.y * 128 * SDIM
                  + (size_t)blockIdx.x * 128;

    const int tid  = threadIdx.x;
    const int warp = tid >> 5;
    const int wm   = warp >> 1;
    const int wn   = warp & 1;
    const int bn0  = blockIdx.x * 128;

    wmma::fragment<wmma::accumulator, 16, 16, 8, float> acc[2][4];
    #pragma unroll
    for (int i = 0; i < 2; i++)
        #pragma unroll
        for (int j = 0; j < 4; j++)
            wmma::fill_fragment(acc[i][j], 0.0f);

    for (int k0 = 0; k0 < SDIM; k0 += 16) {
        // V tile: 128 rows x 16 cols
        #pragma unroll
        for (int i = 0; i < 2; i++) {
            int idx = tid + i * 256;
            int row = idx >> 2;
            int c   = (idx & 3) << 2;
            float4 v = *(const float4*)(Vb + (size_t)row * SDIM + k0 + c);
            As[row][c+0] = to_tf32(v.x);
            As[row][c+1] = to_tf32(v.y);
            As[row][c+2] = to_tf32(v.z);
            As[row][c+3] = to_tf32(v.w);
        }
        // P tile: 16 rows x 128 cols
        #pragma unroll
        for (int i = 0; i < 2; i++) {
            int idx = tid + i * 256;
            int row = idx >> 5;               // 0..15
            int c   = (idx & 31) << 2;        // 0..124
            float4 pv = *(const float4*)(Pb + (size_t)(k0 + row) * SDIM + bn0 + c);
            Bs[row][c+0] = to_tf32(pv.x);
            Bs[row][c+1] = to_tf32(pv.y);
            Bs[row][c+2] = to_tf32(pv.z);
            Bs[row][c+3] = to_tf32(pv.w);
        }
        __syncthreads();

        #pragma unroll
        for (int ks = 0; ks < 16; ks += 8) {
            wmma::fragment<wmma::matrix_a, 16, 16, 8, wmma::precision::tf32, wmma::row_major> af[2];
            wmma::fragment<wmma::matrix_b, 16, 16, 8, wmma::precision::tf32, wmma::row_major> bf[4];
            #pragma unroll
            for (int i = 0; i < 2; i++)
                wmma::load_matrix_sync(af[i], &As[wm * 32 + i * 16][ks], 20);
            #pragma unroll
            for (int j = 0; j < 4; j++)
                wmma::load_matrix_sync(bf[j], &Bs[ks][wn * 64 + j * 16], 132);
            #pragma unroll
            for (int i = 0; i < 2; i++)
                #pragma unroll
                for (int j = 0; j < 4; j++)
                    wmma::mma_sync(acc[i][j], af[i], bf[j], acc[i][j]);
        }
        __syncthreads();
    }

    #pragma unroll
    for (int i = 0; i < 2; i++)
        #pragma unroll
        for (int j = 0; j < 4; j++)
            wmma::store_matrix_sync(
                Ob + (size_t)(wm * 32 + i * 16) * SDIM + wn * 64 + j * 16,
                acc[i][j], SDIM, wmma::mem_row_major);
}

// ---------------------------------------------------------------------------
extern "C" void kernel_launch(void* const* d_in, const int* in_sizes, int n_in,
                              void* d_out, int out_size) {
    (void)in_sizes; (void)n_in; (void)out_size;
    const float* Q = (const float*)d_in[0];
    const float* K = (const float*)d_in[1];
    const float* V = (const float*)d_in[2];
    // d_in[3] = attn_mask (all zeros, unused by the reference)
    float* O = (float*)d_out;

    dim3 grid(SDIM / 128, SDIM / 128, BATCH);
    gemm_qkT_split<<<grid, 256>>>(Q, K);
    softmax_rows<<<BATCH * SDIM, 256>>>();
    gemm_vp<<<grid, 256>>>(V, O);
}

// round 7
// speedup vs baseline: 3.7714x; 3.7714x over previous
#include <cuda_runtime.h>
#include <mma.h>
#include <cstdint>
#include <cstddef>

using namespace nvcuda;

#define SDIM 2048
#define BATCH 8
#define NELEM ((size_t)BATCH * SDIM * SDIM)

// Softmax(P) scratch: 134 MB device global (module-load allocated).
__device__ float g_P[NELEM];

// Arch-specific ("a") device compilation => tcgen05 available.
#if defined(__CUDA_ARCH_FEAT_SM103_ALL) || defined(__CUDA_ARCH_FEAT_SM100_ALL) || defined(__CUDA_ARCH_FEAT_SM101_ALL)
#define HAS_TC05 1
#else
#define HAS_TC05 0
#endif

__device__ __forceinline__ float to_tf32(float x) {
    float r;
    asm("cvt.rna.tf32.f32 %0, %1;" : "=f"(r) : "f"(x));
    return r;
}

__device__ __forceinline__ uint32_t smem_u32(const void* p) {
    uint32_t a;
    asm("{ .reg .u64 t; cvta.to.shared.u64 t, %1; cvt.u32.u64 %0, t; }" : "=r"(a) : "l"(p));
    return a;
}

#if defined(__CUDA_ARCH__)
__device__ __forceinline__ uint32_t elect_one() {
    uint32_t pred;
    asm volatile("{\n\t.reg .pred p;\n\telect.sync _|p, 0xFFFFFFFF;\n\tselp.b32 %0, 1, 0, p;\n\t}"
                 : "=r"(pred));
    return pred;
}
#endif

// SW128 K-major smem descriptor (layout=SW128, version=1, SBO=64, LBO=1).
__device__ __forceinline__ uint64_t make_desc_sw128(uint32_t addr) {
    const uint64_t base = (uint64_t(2) << 61) | (uint64_t(1) << 46)
                        | (uint64_t(64) << 32) | (uint64_t(1) << 16);
    return base | ((uint64_t)(addr >> 4) & 0x3FFF);
}

__device__ __forceinline__ void mbar_init(uint32_t mbar, uint32_t cnt) {
    asm volatile("mbarrier.init.shared.b64 [%0], %1;" :: "r"(mbar), "r"(cnt) : "memory");
}
__device__ __forceinline__ void mbar_inval(uint32_t mbar) {
    asm volatile("mbarrier.inval.shared.b64 [%0];" :: "r"(mbar) : "memory");
}
__device__ __forceinline__ void mbar_wait(uint32_t mbar, uint32_t phase) {
    asm volatile(
        "{\n\t.reg .pred P;\n\t"
        "WL_%=:\n\t"
        "mbarrier.try_wait.parity.acquire.cta.shared::cta.b64 P, [%0], %1, 0x989680;\n\t"
        "@P bra.uni WD_%=;\n\t"
        "bra.uni WL_%=;\n\t"
        "WD_%=:\n\t}"
        :: "r"(mbar), "r"(phase) : "memory");
}

#if HAS_TC05
__device__ __forceinline__ void mma_tf32_ss(uint32_t d_tmem, uint64_t a_desc, uint64_t b_desc,
                                            uint32_t idesc, uint32_t en) {
    asm volatile(
        "{\n\t.reg .pred p;\n\t"
        "setp.ne.u32 p, %5, 0;\n\t"
        "tcgen05.mma.cta_group::1.kind::tf32 [%0], %1, %2, %3, {%4,%4,%4,%4}, p;\n\t}"
        :: "r"(d_tmem), "l"(a_desc), "l"(b_desc), "r"(idesc), "r"(0u), "r"(en)
        : "memory");
}
__device__ __forceinline__ void tc_commit(uint32_t mbar) {
    asm volatile("tcgen05.commit.cta_group::1.mbarrier::arrive::one.shared::cluster.b64 [%0];"
                 :: "r"(mbar) : "memory");
}
// Warp-collective: read 32 cols x 32 lanes of f32 from TMEM, store row to gmem.
__device__ __forceinline__ void tmem_ld32_store(uint32_t taddr, float* gdst) {
    uint32_t r[32];
    asm volatile(
        "tcgen05.ld.sync.aligned.32x32b.x32.b32 "
        "{%0, %1, %2, %3, %4, %5, %6, %7, "
        " %8, %9, %10, %11, %12, %13, %14, %15, "
        " %16, %17, %18, %19, %20, %21, %22, %23, "
        " %24, %25, %26, %27, %28, %29, %30, %31}, [%32];"
        : "=r"(r[0]),  "=r"(r[1]),  "=r"(r[2]),  "=r"(r[3]),
          "=r"(r[4]),  "=r"(r[5]),  "=r"(r[6]),  "=r"(r[7]),
          "=r"(r[8]),  "=r"(r[9]),  "=r"(r[10]), "=r"(r[11]),
          "=r"(r[12]), "=r"(r[13]), "=r"(r[14]), "=r"(r[15]),
          "=r"(r[16]), "=r"(r[17]), "=r"(r[18]), "=r"(r[19]),
          "=r"(r[20]), "=r"(r[21]), "=r"(r[22]), "=r"(r[23]),
          "=r"(r[24]), "=r"(r[25]), "=r"(r[26]), "=r"(r[27]),
          "=r"(r[28]), "=r"(r[29]), "=r"(r[30]), "=r"(r[31])
        : "r"(taddr));
    asm volatile("tcgen05.wait::ld.sync.aligned;" ::: "memory");
    #pragma unroll
    for (int j = 0; j < 8; j++) {
        float4 v;
        v.x = __uint_as_float(r[4 * j + 0]);
        v.y = __uint_as_float(r[4 * j + 1]);
        v.z = __uint_as_float(r[4 * j + 2]);
        v.w = __uint_as_float(r[4 * j + 3]);
        *(float4*)(gdst + 4 * j) = v;
    }
}
#endif

// Tile geometry (both GEMMs): CTA 128x128, BK=32, grid (16,16,8), 256 threads.
#define G_BM 128
#define G_BN 128
#define G_BK 32
#define G_NKT (SDIM / G_BK)     // 64
// idesc: c=F32(1@4), a=TF32(2@7), b=TF32(2@10), N/8@17, M/16@24
#define G_IDESC ((1u << 4) | (2u << 7) | (2u << 10) | ((G_BN / 8) << 17) | ((G_BM / 16) << 24))

#define G1_STAGE 65536                       // Ah 16K | Al 16K | Bh 16K | Bl 16K
#define G1_DYN   (2 * G1_STAGE + 1024)
#define G2_STAGE 32768                       // A 16K | B 16K
#define G2_DYN   (2 * G2_STAGE + 1024)

// ===========================================================================
// GEMM 1: P = Q @ K^T (NT), 2-split tf32 (3 MMA terms).
// ===========================================================================
__global__ __launch_bounds__(256, 1) __cluster_dims__(1, 1, 1)
void gemm1_k(const float* __restrict__ Q, const float* __restrict__ K) {
#if HAS_TC05
    extern __shared__ char dyn[];
    __shared__ __align__(16) uint64_t s_mbar[2];
    __shared__ uint32_t s_tmem[1];

    const uint32_t raw = smem_u32(dyn);
    char* base = dyn + (((raw + 1023u) & ~1023u) - raw);

    const int tid = threadIdx.x;
    const int wid = tid >> 5;
    const int lid = tid & 31;
    const int b   = blockIdx.z;
    const int mt  = blockIdx.y;
    const int nt  = blockIdx.x;
    const size_t bo = (size_t)b * SDIM * SDIM;
    const float* Qb = Q + bo + (size_t)mt * G_BM * SDIM;
    const float* Kb = K + bo + (size_t)nt * G_BN * SDIM;

    const uint32_t mb0 = smem_u32(&s_mbar[0]);
    const uint32_t mb1 = mb0 + 8;

    if (wid == 0) {
        asm volatile("tcgen05.alloc.cta_group::1.sync.aligned.shared::cta.b32 [%0], %1;"
                     :: "r"(smem_u32(s_tmem)), "r"(128u) : "memory");
    }
    if (tid == 0) { mbar_init(mb0, 1); mbar_init(mb1, 1); }
    __syncthreads();
    const uint32_t tmem = s_tmem[0];

    // Per-thread staging map: idx = tid + j*256 -> row = idx>>3, 16B col = (idx&7)*16
    int   rowi[4];
    uint32_t offi[4];
    #pragma unroll
    for (int j = 0; j < 4; j++) {
        int i = tid + j * 256;
        rowi[j] = i >> 3;
        uint32_t off = ((uint32_t)(i >> 3) << 7) | ((uint32_t)(i & 7) << 4);
        off ^= (off >> 3) & 0x70;
        offi[j] = off;
    }

    float4 qv[4], kv[4];
    // Prefetch kt=0
    #pragma unroll
    for (int j = 0; j < 4; j++) {
        const size_t co = (size_t)(tid + j * 256 & 7) * 4;   // 4-float col offset
        qv[j] = *(const float4*)(Qb + (size_t)rowi[j] * SDIM + co);
        kv[j] = *(const float4*)(Kb + (size_t)rowi[j] * SDIM + co);
    }

    uint32_t ph[2] = {0, 0};

    for (int kt = 0; kt < G_NKT; kt++) {
        const int buf = kt & 1;
        char* sb = base + buf * G1_STAGE;
        if (kt >= 2) {
            mbar_wait(buf == 0 ? mb0 : mb1, ph[buf]);
            ph[buf] ^= 1;
        }
        // Convert + store staged registers (hi/lo split).
        #pragma unroll
        for (int j = 0; j < 4; j++) {
            float4 q = qv[j], k = kv[j], h4, l4;
            h4.x = to_tf32(q.x); l4.x = to_tf32(q.x - h4.x);
            h4.y = to_tf32(q.y); l4.y = to_tf32(q.y - h4.y);
            h4.z = to_tf32(q.z); l4.z = to_tf32(q.z - h4.z);
            h4.w = to_tf32(q.w); l4.w = to_tf32(q.w - h4.w);
            *(float4*)(sb +         offi[j]) = h4;
            *(float4*)(sb + 16384 + offi[j]) = l4;
            h4.x = to_tf32(k.x); l4.x = to_tf32(k.x - h4.x);
            h4.y = to_tf32(k.y); l4.y = to_tf32(k.y - h4.y);
            h4.z = to_tf32(k.z); l4.z = to_tf32(k.z - h4.z);
            h4.w = to_tf32(k.w); l4.w = to_tf32(k.w - h4.w);
            *(float4*)(sb + 32768 + offi[j]) = h4;
            *(float4*)(sb + 49152 + offi[j]) = l4;
        }
        asm volatile("fence.proxy.async.shared::cta;" ::: "memory");
        __syncthreads();

        // Prefetch next tile (hidden behind MMA).
        if (kt + 1 < G_NKT) {
            const size_t k0 = (size_t)(kt + 1) * G_BK;
            #pragma unroll
            for (int j = 0; j < 4; j++) {
                const size_t co = k0 + (size_t)((tid + j * 256) & 7) * 4;
                qv[j] = *(const float4*)(Qb + (size_t)rowi[j] * SDIM + co);
                kv[j] = *(const float4*)(Kb + (size_t)rowi[j] * SDIM + co);
            }
        }

        if (wid == 0 && elect_one()) {
            const uint32_t sa = smem_u32(sb);
            const uint64_t dAh = make_desc_sw128(sa);
            const uint64_t dAl = make_desc_sw128(sa + 16384);
            const uint64_t dBh = make_desc_sw128(sa + 32768);
            const uint64_t dBl = make_desc_sw128(sa + 49152);
            #pragma unroll
            for (int ks = 0; ks < 4; ks++) {
                const uint64_t o = (uint64_t)(ks * 2);
                mma_tf32_ss(tmem, dAh + o, dBh + o, G_IDESC, (kt > 0 || ks > 0) ? 1u : 0u);
                mma_tf32_ss(tmem, dAh + o, dBl + o, G_IDESC, 1u);
                mma_tf32_ss(tmem, dAl + o, dBh + o, G_IDESC, 1u);
            }
            tc_commit(buf == 0 ? mb0 : mb1);
        }
    }

    mbar_wait(mb0, ph[0]);
    mbar_wait(mb1, ph[1]);
    asm volatile("tcgen05.fence::after_thread_sync;" ::: "memory");

    // Epilogue: warp w -> rows (w&3)*32+lid, cols (w>>2)*64 .. +63.
    {
        const int sub  = wid & 3;
        const int half = wid >> 2;
        const int row  = sub * 32 + lid;
        float* Cb = g_P + bo + ((size_t)mt * G_BM + row) * SDIM
                         + (size_t)nt * G_BN + (size_t)half * 64;
        tmem_ld32_store(tmem + (uint32_t)(half * 64),      Cb);
        tmem_ld32_store(tmem + (uint32_t)(half * 64 + 32), Cb + 32);
    }

    __syncthreads();
    if (tid == 0) { mbar_inval(mb0); mbar_inval(mb1); }
    __syncthreads();
    if (wid == 0) {
        asm volatile("tcgen05.relinquish_alloc_permit.cta_group::1.sync.aligned;");
        asm volatile("tcgen05.dealloc.cta_group::1.sync.aligned.b32 %0, %1;"
                     :: "r"(tmem), "r"(128u));
    }
#else
    // ---------- Fallback: wmma tf32 (round-2, known-correct) ----------
    __shared__ __align__(16) float Ah[128][20];
    __shared__ __align__(16) float Al[128][20];
    __shared__ __align__(16) float Bh[128][20];
    __shared__ __align__(16) float Bl[128][20];

    const int b = blockIdx.z;
    const float* Qb = Q + (size_t)b * SDIM * SDIM + (size_t)blockIdx.y * 128 * SDIM;
    const float* Kb = K + (size_t)b * SDIM * SDIM + (size_t)blockIdx.x * 128 * SDIM;
    float* Cb = g_P + (size_t)b * SDIM * SDIM + (size_t)blockIdx.y * 128 * SDIM
                    + (size_t)blockIdx.x * 128;

    const int tid  = threadIdx.x;
    const int warp = tid >> 5;
    const int wm   = warp >> 1;
    const int wn   = warp & 1;

    wmma::fragment<wmma::accumulator, 16, 16, 8, float> acc[2][4];
    #pragma unroll
    for (int i = 0; i < 2; i++)
        #pragma unroll
        for (int j = 0; j < 4; j++)
            wmma::fill_fragment(acc[i][j], 0.0f);

    for (int k0 = 0; k0 < SDIM; k0 += 16) {
        #pragma unroll
        for (int i = 0; i < 2; i++) {
            int idx = tid + i * 256;
            int row = idx >> 2;
            int c   = (idx & 3) << 2;
            float4 q = *(const float4*)(Qb + (size_t)row * SDIM + k0 + c);
            float4 k = *(const float4*)(Kb + (size_t)row * SDIM + k0 + c);
            float h;
            h = to_tf32(q.x); Ah[row][c+0] = h; Al[row][c+0] = to_tf32(q.x - h);
            h = to_tf32(q.y); Ah[row][c+1] = h; Al[row][c+1] = to_tf32(q.y - h);
            h = to_tf32(q.z); Ah[row][c+2] = h; Al[row][c+2] = to_tf32(q.z - h);
            h = to_tf32(q.w); Ah[row][c+3] = h; Al[row][c+3] = to_tf32(q.w - h);
            h = to_tf32(k.x); Bh[row][c+0] = h; Bl[row][c+0] = to_tf32(k.x - h);
            h = to_tf32(k.y); Bh[row][c+1] = h; Bl[row][c+1] = to_tf32(k.y - h);
            h = to_tf32(k.z); Bh[row][c+2] = h; Bl[row][c+2] = to_tf32(k.z - h);
            h = to_tf32(k.w); Bh[row][c+3] = h; Bl[row][c+3] = to_tf32(k.w - h);
        }
        __syncthreads();
        #pragma unroll
        for (int ks = 0; ks < 16; ks += 8) {
            wmma::fragment<wmma::matrix_a, 16, 16, 8, wmma::precision::tf32, wmma::row_major> ah[2], al[2];
            wmma::fragment<wmma::matrix_b, 16, 16, 8, wmma::precision::tf32, wmma::col_major> bh[4], bl[4];
            #pragma unroll
            for (int i = 0; i < 2; i++) {
                wmma::load_matrix_sync(ah[i], &Ah[wm * 32 + i * 16][ks], 20);
                wmma::load_matrix_sync(al[i], &Al[wm * 32 + i * 16][ks], 20);
            }
            #pragma unroll
            for (int j = 0; j < 4; j++) {
                wmma::load_matrix_sync(bh[j], &Bh[wn * 64 + j * 16][ks], 20);
                wmma::load_matrix_sync(bl[j], &Bl[wn * 64 + j * 16][ks], 20);
            }
            #pragma unroll
            for (int i = 0; i < 2; i++)
                #pragma unroll
                for (int j = 0; j < 4; j++) {
                    wmma::mma_sync(acc[i][j], ah[i], bh[j], acc[i][j]);
                    wmma::mma_sync(acc[i][j], ah[i], bl[j], acc[i][j]);
                    wmma::mma_sync(acc[i][j], al[i], bh[j], acc[i][j]);
                }
        }
        __syncthreads();
    }
    #pragma unroll
    for (int i = 0; i < 2; i++)
        #pragma unroll
        for (int j = 0; j < 4; j++)
            wmma::store_matrix_sync(
                Cb + (size_t)(wm * 32 + i * 16) * SDIM + wn * 64 + j * 16,
                acc[i][j], SDIM, wmma::mem_row_major);
#endif
}

// ===========================================================================
// Softmax over last dim, in place on g_P.
// ===========================================================================
__global__ __launch_bounds__(256)
void softmax_rows() {
    __shared__ float red[8];
    float* p = g_P + (size_t)blockIdx.x * SDIM;
    const int tid  = threadIdx.x;
    const int lane = tid & 31;
    const int warp = tid >> 5;

    float4 a = *(const float4*)(p + tid * 4);
    float4 b = *(const float4*)(p + 1024 + tid * 4);

    float m = fmaxf(fmaxf(fmaxf(a.x, a.y), fmaxf(a.z, a.w)),
                    fmaxf(fmaxf(b.x, b.y), fmaxf(b.z, b.w)));
    #pragma unroll
    for (int o = 16; o > 0; o >>= 1)
        m = fmaxf(m, __shfl_xor_sync(0xffffffffu, m, o));
    if (lane == 0) red[warp] = m;
    __syncthreads();
    m = red[0];
    #pragma unroll
    for (int i = 1; i < 8; i++) m = fmaxf(m, red[i]);
    __syncthreads();

    a.x = expf(a.x - m); a.y = expf(a.y - m); a.z = expf(a.z - m); a.w = expf(a.w - m);
    b.x = expf(b.x - m); b.y = expf(b.y - m); b.z = expf(b.z - m); b.w = expf(b.w - m);

    float s = (a.x + a.y) + (a.z + a.w) + (b.x + b.y) + (b.z + b.w);
    #pragma unroll
    for (int o = 16; o > 0; o >>= 1)
        s += __shfl_xor_sync(0xffffffffu, s, o);
    if (lane == 0) red[warp] = s;
    __syncthreads();
    s = red[0] + red[1] + red[2] + red[3] + red[4] + red[5] + red[6] + red[7];

    const float r = 1.0f / s;
    a.x *= r; a.y *= r; a.z *= r; a.w *= r;
    b.x *= r; b.y *= r; b.z *= r; b.w *= r;
    *(float4*)(p + tid * 4)        = a;
    *(float4*)(p + 1024 + tid * 4) = b;
}

// ===========================================================================
// GEMM 2: out = V @ P (NN), single tf32. P tile transposed during staging.
// ===========================================================================
__global__ __launch_bounds__(256, 1) __cluster_dims__(1, 1, 1)
void gemm2_k(const float* __restrict__ V, float* __restrict__ O) {
#if HAS_TC05
    extern __shared__ char dyn[];
    __shared__ __align__(16) uint64_t s_mbar[2];
    __shared__ uint32_t s_tmem[1];

    const uint32_t raw = smem_u32(dyn);
    char* base = dyn + (((raw + 1023u) & ~1023u) - raw);

    const int tid = threadIdx.x;
    const int wid = tid >> 5;
    const int lid = tid & 31;
    const int b   = blockIdx.z;
    const int mt  = blockIdx.y;
    const int nt  = blockIdx.x;
    const size_t bo  = (size_t)b * SDIM * SDIM;
    const int    bn0 = nt * G_BN;
    const float* Vb = V   + bo + (size_t)mt * G_BM * SDIM;
    const float* Pb = g_P + bo;

    const uint32_t mb0 = smem_u32(&s_mbar[0]);
    const uint32_t mb1 = mb0 + 8;

    if (wid == 0) {
        asm volatile("tcgen05.alloc.cta_group::1.sync.aligned.shared::cta.b32 [%0], %1;"
                     :: "r"(smem_u32(s_tmem)), "r"(128u) : "memory");
    }
    if (tid == 0) { mbar_init(mb0, 1); mbar_init(mb1, 1); }
    __syncthreads();
    const uint32_t tmem = s_tmem[0];

    // A map (V, K-major): idx = tid + j*256 -> row=idx>>3, col16=(idx&7)*16
    int      arow[4];
    uint32_t aoff[4];
    // B map (P transpose): idx -> n = idx&127, k0 = (idx>>7)*4
    int      bn[4], bk0[4];
    uint32_t boff[4];
    #pragma unroll
    for (int j = 0; j < 4; j++) {
        int i = tid + j * 256;
        arow[j] = i >> 3;
        uint32_t off = ((uint32_t)(i >> 3) << 7) | ((uint32_t)(i & 7) << 4);
        off ^= (off >> 3) & 0x70;
        aoff[j] = off;
        bn[j]  = i & 127;
        bk0[j] = (i >> 7) * 4;
        uint32_t bo2 = ((uint32_t)(i & 127) << 7) | ((uint32_t)bk0[j] << 2);
        bo2 ^= (bo2 >> 3) & 0x70;
        boff[j] = bo2;
    }

    float4 av[4];
    float  pv[4][4];
    // Prefetch kt=0
    #pragma unroll
    for (int j = 0; j < 4; j++) {
        const size_t co = (size_t)((tid + j * 256) & 7) * 4;
        av[j] = *(const float4*)(Vb + (size_t)arow[j] * SDIM + co);
        #pragma unroll
        for (int jj = 0; jj < 4; jj++)
            pv[j][jj] = Pb[(size_t)(bk0[j] + jj) * SDIM + bn0 + bn[j]];
    }

    uint32_t ph[2] = {0, 0};

    for (int kt = 0; kt < G_NKT; kt++) {
        const int buf = kt & 1;
        char* sb = base + buf * G2_STAGE;
        if (kt >= 2) {
            mbar_wait(buf == 0 ? mb0 : mb1, ph[buf]);
            ph[buf] ^= 1;
        }
        #pragma unroll
        for (int j = 0; j < 4; j++) {
            float4 v = av[j];
            v.x = to_tf32(v.x); v.y = to_tf32(v.y);
            v.z = to_tf32(v.z); v.w = to_tf32(v.w);
            *(float4*)(sb + aoff[j]) = v;
            float4 t;
            t.x = to_tf32(pv[j][0]); t.y = to_tf32(pv[j][1]);
            t.z = to_tf32(pv[j][2]); t.w = to_tf32(pv[j][3]);
            *(float4*)(sb + 16384 + boff[j]) = t;
        }
        asm volatile("fence.proxy.async.shared::cta;" ::: "memory");
        __syncthreads();

        if (kt + 1 < G_NKT) {
            const size_t k0 = (size_t)(kt + 1) * G_BK;
            #pragma unroll
            for (int j = 0; j < 4; j++) {
                const size_t co = k0 + (size_t)((tid + j * 256) & 7) * 4;
                av[j] = *(const float4*)(Vb + (size_t)arow[j] * SDIM + co);
                #pragma unroll
                for (int jj = 0; jj < 4; jj++)
                    pv[j][jj] = Pb[(k0 + (size_t)(bk0[j] + jj)) * SDIM + bn0 + bn[j]];
            }
        }

        if (wid == 0 && elect_one()) {
            const uint32_t sa = smem_u32(sb);
            const uint64_t dA = make_desc_sw128(sa);
            const uint64_t dB = make_desc_sw128(sa + 16384);
            #pragma unroll
            for (int ks = 0; ks < 4; ks++) {
                const uint64_t o = (uint64_t)(ks * 2);
                mma_tf32_ss(tmem, dA + o, dB + o, G_IDESC, (kt > 0 || ks > 0) ? 1u : 0u);
            }
            tc_commit(buf == 0 ? mb0 : mb1);
        }
    }

    mbar_wait(mb0, ph[0]);
    mbar_wait(mb1, ph[1]);
    asm volatile("tcgen05.fence::after_thread_sync;" ::: "memory");

    {
        const int sub  = wid & 3;
        const int half = wid >> 2;
        const int row  = sub * 32 + lid;
        float* Ob = O + bo + ((size_t)mt * G_BM + row) * SDIM
                       + (size_t)nt * G_BN + (size_t)half * 64;
        tmem_ld32_store(tmem + (uint32_t)(half * 64),      Ob);
        tmem_ld32_store(tmem + (uint32_t)(half * 64 + 32), Ob + 32);
    }

    __syncthreads();
    if (tid == 0) { mbar_inval(mb0); mbar_inval(mb1); }
    __syncthreads();
    if (wid == 0) {
        asm volatile("tcgen05.relinquish_alloc_permit.cta_group::1.sync.aligned;");
        asm volatile("tcgen05.dealloc.cta_group::1.sync.aligned.b32 %0, %1;"
                     :: "r"(tmem), "r"(128u));
    }
#else
    // ---------- Fallback: wmma tf32 (round-2, known-correct) ----------
    __shared__ __align__(16) float As[128][20];
    __shared__ __align__(16) float Bs[16][132];

    const int b = blockIdx.z;
    const float* Vb = V + (size_t)b * SDIM * SDIM + (size_t)blockIdx.y * 128 * SDIM;
    const float* Pb = g_P + (size_t)b * SDIM * SDIM;
    float* Ob = O + (size_t)b * SDIM * SDIM + (size_t)blockIdx.y * 128 * SDIM
                  + (size_t)blockIdx.x * 128;

    const int tid  = threadIdx.x;
    const int warp = tid >> 5;
    const int wm   = warp >> 1;
    const int wn   = warp & 1;
    const int bn0  = blockIdx.x * 128;

    wmma::fragment<wmma::accumulator, 16, 16, 8, float> acc[2][4];
    #pragma unroll
    for (int i = 0; i < 2; i++)
        #pragma unroll
        for (int j = 0; j < 4; j++)
            wmma::fill_fragment(acc[i][j], 0.0f);

    for (int k0 = 0; k0 < SDIM; k0 += 16) {
        #pragma unroll
        for (int i = 0; i < 2; i++) {
            int idx = tid + i * 256;
            int row = idx >> 2;
            int c   = (idx & 3) << 2;
            float4 v = *(const float4*)(Vb + (size_t)row * SDIM + k0 + c);
            As[row][c+0] = to_tf32(v.x);
            As[row][c+1] = to_tf32(v.y);
            As[row][c+2] = to_tf32(v.z);
            As[row][c+3] = to_tf32(v.w);
        }
        #pragma unroll
        for (int i = 0; i < 2; i++) {
            int idx = tid + i * 256;
            int row = idx >> 5;
            int c   = (idx & 31) << 2;
            float4 pvv = *(const float4*)(Pb + (size_t)(k0 + row) * SDIM + bn0 + c);
            Bs[row][c+0] = to_tf32(pvv.x);
            Bs[row][c+1] = to_tf32(pvv.y);
            Bs[row][c+2] = to_tf32(pvv.z);
            Bs[row][c+3] = to_tf32(pvv.w);
        }
        __syncthreads();
        #pragma unroll
        for (int ks = 0; ks < 16; ks += 8) {
            wmma::fragment<wmma::matrix_a, 16, 16, 8, wmma::precision::tf32, wmma::row_major> af[2];
            wmma::fragment<wmma::matrix_b, 16, 16, 8, wmma::precision::tf32, wmma::row_major> bf[4];
            #pragma unroll
            for (int i = 0; i < 2; i++)
                wmma::load_matrix_sync(af[i], &As[wm * 32 + i * 16][ks], 20);
            #pragma unroll
            for (int j = 0; j < 4; j++)
                wmma::load_matrix_sync(bf[j], &Bs[ks][wn * 64 + j * 16], 132);
            #pragma unroll
            for (int i = 0; i < 2; i++)
                #pragma unroll
                for (int j = 0; j < 4; j++)
                    wmma::mma_sync(acc[i][j], af[i], bf[j], acc[i][j]);
        }
        __syncthreads();
    }
    #pragma unroll
    for (int i = 0; i < 2; i++)
        #pragma unroll
        for (int j = 0; j < 4; j++)
            wmma::store_matrix_sync(
                Ob + (size_t)(wm * 32 + i * 16) * SDIM + wn * 64 + j * 16,
                acc[i][j], SDIM, wmma::mem_row_major);
#endif
}

// ===========================================================================
extern "C" void kernel_launch(void* const* d_in, const int* in_sizes, int n_in,
                              void* d_out, int out_size) {
    (void)in_sizes; (void)n_in; (void)out_size;
    const float* Q = (const float*)d_in[0];
    const float* K = (const float*)d_in[1];
    const float* V = (const float*)d_in[2];
    float* O = (float*)d_out;

    cudaFuncSetAttribute((const void*)gemm1_k,
                         cudaFuncAttributeMaxDynamicSharedMemorySize, G1_DYN);
    cudaFuncSetAttribute((const void*)gemm2_k,
                         cudaFuncAttributeMaxDynamicSharedMemorySize, G2_DYN);

    dim3 grid(SDIM / G_BN, SDIM / G_BM, BATCH);
    gemm1_k<<<grid, 256, G1_DYN>>>(Q, K);
    softmax_rows<<<BATCH * SDIM, 256>>>();
    gemm2_k<<<grid, 256, G2_DYN>>>(V, O);
}

// round 11
// speedup vs baseline: 9.1176x; 2.4176x over previous
#include <cuda_runtime.h>
#include <cuda_fp16.h>
#include <cstdint>
#include <cstddef>

#define SDIM 2048
#define BATCH 8
#define NELEM ((size_t)BATCH * SDIM * SDIM)

// Device-global scratch (module-load allocated; no runtime allocation).
__device__ float g_P [NELEM];                       // P then softmax(P)
__device__ float g_Pt[NELEM];                       // softmax(P)^T, tf32-rounded
__device__ __align__(16) __half g_Qh16[NELEM];
__device__ __align__(16) __half g_Ql16[NELEM];      // (q - qh) * 4096
__device__ __align__(16) __half g_Kh16[NELEM];
__device__ __align__(16) __half g_Kl16[NELEM];      // (k - kh) * 4096

#if defined(__CUDA_ARCH_FEAT_SM103_ALL) || defined(__CUDA_ARCH_FEAT_SM100_ALL) || defined(__CUDA_ARCH_FEAT_SM101_ALL)
#define HAS_TC05 1
#else
#define HAS_TC05 0
#endif

__device__ __forceinline__ float to_tf32(float x) {
    float r;
    asm("cvt.rna.tf32.f32 %0, %1;" : "=f"(r) : "f"(x));
    return r;
}
__device__ __forceinline__ uint32_t smem_u32(const void* p) {
    uint32_t a;
    asm("{ .reg .u64 t; cvta.to.shared.u64 t, %1; cvt.u32.u64 %0, t; }" : "=r"(a) : "l"(p));
    return a;
}
__device__ __forceinline__ uint32_t elect_one() {
    uint32_t pred;
    asm volatile("{\n\t.reg .pred p;\n\telect.sync _|p, 0xFFFFFFFF;\n\tselp.b32 %0, 1, 0, p;\n\t}"
                 : "=r"(pred));
    return pred;
}
__device__ __forceinline__ uint32_t swz(uint32_t off) {   // SW128 swizzle
    return off ^ ((off >> 3) & 0x70);
}
__device__ __forceinline__ uint64_t make_desc_sw128(uint32_t addr) {
    const uint64_t base = (uint64_t(2) << 61) | (uint64_t(1) << 46)
                        | (uint64_t(64) << 32) | (uint64_t(1) << 16);
    return base | ((uint64_t)(addr >> 4) & 0x3FFF);
}
__device__ __forceinline__ void mbar_init(uint32_t mbar, uint32_t cnt) {
    asm volatile("mbarrier.init.shared.b64 [%0], %1;" :: "r"(mbar), "r"(cnt) : "memory");
}
__device__ __forceinline__ void mbar_inval(uint32_t mbar) {
    asm volatile("mbarrier.inval.shared.b64 [%0];" :: "r"(mbar) : "memory");
}
__device__ __forceinline__ void mbar_wait(uint32_t mbar, uint32_t phase) {
    asm volatile(
        "{\n\t.reg .pred P;\n\t"
        "WL_%=:\n\t"
        "mbarrier.try_wait.parity.acquire.cta.shared::cta.b64 P, [%0], %1, 0x989680;\n\t"
        "@P bra.uni WD_%=;\n\t"
        "bra.uni WL_%=;\n\t"
        "WD_%=:\n\t}"
        :: "r"(mbar), "r"(phase) : "memory");
}
__device__ __forceinline__ void cp16(uint32_t smem, const void* g) {
    asm volatile("cp.async.cg.shared.global [%0], [%1], 16;" :: "r"(smem), "l"(g));
}
__device__ __forceinline__ void cp_commit() {
    asm volatile("cp.async.commit_group;" ::: "memory");
}

#if HAS_TC05
__device__ __forceinline__ void mma_f16_ss(uint32_t d_tmem, uint64_t a_desc, uint64_t b_desc,
                                           uint32_t idesc, uint32_t en) {
    asm volatile(
        "{\n\t.reg .pred p;\n\t"
        "setp.ne.u32 p, %5, 0;\n\t"
        "tcgen05.mma.cta_group::1.kind::f16 [%0], %1, %2, %3, {%4,%4,%4,%4}, p;\n\t}"
        :: "r"(d_tmem), "l"(a_desc), "l"(b_desc), "r"(idesc), "r"(0u), "r"(en)
        : "memory");
}
__device__ __forceinline__ void mma_tf32_ss(uint32_t d_tmem, uint64_t a_desc, uint64_t b_desc,
                                            uint32_t idesc, uint32_t en) {
    asm volatile(
        "{\n\t.reg .pred p;\n\t"
        "setp.ne.u32 p, %5, 0;\n\t"
        "tcgen05.mma.cta_group::1.kind::tf32 [%0], %1, %2, %3, {%4,%4,%4,%4}, p;\n\t}"
        :: "r"(d_tmem), "l"(a_desc), "l"(b_desc), "r"(idesc), "r"(0u), "r"(en)
        : "memory");
}
__device__ __forceinline__ void tc_commit(uint32_t mbar) {
    asm volatile("tcgen05.commit.cta_group::1.mbarrier::arrive::one.shared::cluster.b64 [%0];"
                 :: "r"(mbar) : "memory");
}
__device__ __forceinline__ void tmem_ld32(uint32_t* r, uint32_t taddr) {
    asm volatile(
        "tcgen05.ld.sync.aligned.32x32b.x32.b32 "
        "{%0, %1, %2, %3, %4, %5, %6, %7, "
        " %8, %9, %10, %11, %12, %13, %14, %15, "
        " %16, %17, %18, %19, %20, %21, %22, %23, "
        " %24, %25, %26, %27, %28, %29, %30, %31}, [%32];"
        : "=r"(r[0]),  "=r"(r[1]),  "=r"(r[2]),  "=r"(r[3]),
          "=r"(r[4]),  "=r"(r[5]),  "=r"(r[6]),  "=r"(r[7]),
          "=r"(r[8]),  "=r"(r[9]),  "=r"(r[10]), "=r"(r[11]),
          "=r"(r[12]), "=r"(r[13]), "=r"(r[14]), "=r"(r[15]),
          "=r"(r[16]), "=r"(r[17]), "=r"(r[18]), "=r"(r[19]),
          "=r"(r[20]), "=r"(r[21]), "=r"(r[22]), "=r"(r[23]),
          "=r"(r[24]), "=r"(r[25]), "=r"(r[26]), "=r"(r[27]),
          "=r"(r[28]), "=r"(r[29]), "=r"(r[30]), "=r"(r[31])
        : "r"(taddr));
    asm volatile("tcgen05.wait::ld.sync.aligned;" ::: "memory");
}
#endif

// ===========================================================================
// Pass 0: split Q,K into f16 hi + scaled-lo arrays.
// ===========================================================================
__global__ __launch_bounds__(256)
void split16(const float* __restrict__ Q, const float* __restrict__ K) {
    size_t i = (size_t)blockIdx.x * 256 + threadIdx.x;   // float4 index
    float4 q = ((const float4*)Q)[i];
    float4 k = ((const float4*)K)[i];

    __half h[4], l[4];
    h[0] = __float2half_rn(q.x); l[0] = __float2half_rn((q.x - __half2float(h[0])) * 4096.f);
    h[1] = __float2half_rn(q.y); l[1] = __float2half_rn((q.y - __half2float(h[1])) * 4096.f);
    h[2] = __float2half_rn(q.z); l[2] = __float2half_rn((q.z - __half2float(h[2])) * 4096.f);
    h[3] = __float2half_rn(q.w); l[3] = __float2half_rn((q.w - __half2float(h[3])) * 4096.f);
    ((__half2*)g_Qh16)[i*2]   = __halves2half2(h[0], h[1]);
    ((__half2*)g_Qh16)[i*2+1] = __halves2half2(h[2], h[3]);
    ((__half2*)g_Ql16)[i*2]   = __halves2half2(l[0], l[1]);
    ((__half2*)g_Ql16)[i*2+1] = __halves2half2(l[2], l[3]);

    h[0] = __float2half_rn(k.x); l[0] = __float2half_rn((k.x - __half2float(h[0])) * 4096.f);
    h[1] = __float2half_rn(k.y); l[1] = __float2half_rn((k.y - __half2float(h[1])) * 4096.f);
    h[2] = __float2half_rn(k.z); l[2] = __float2half_rn((k.z - __half2float(h[2])) * 4096.f);
    h[3] = __float2half_rn(k.w); l[3] = __float2half_rn((k.w - __half2float(h[3])) * 4096.f);
    ((__half2*)g_Kh16)[i*2]   = __halves2half2(h[0], h[1]);
    ((__half2*)g_Kh16)[i*2+1] = __halves2half2(h[2], h[3]);
    ((__half2*)g_Kl16)[i*2]   = __halves2half2(l[0], l[1]);
    ((__half2*)g_Kl16)[i*2+1] = __halves2half2(l[2], l[3]);
}

// ===========================================================================
// Pass 1: P = Q @ K^T via f16 2-split tcgen05. CTA 128x256, BK=64 f16.
//   Dhh (tmem+0)   += Qh.Kh
//   Dx  (tmem+256) += Qh.Kl' + Ql'.Kh     (4096x scaled)
//   P = Dhh + Dx/4096
// ===========================================================================
#define G1_NKT   32
#define G1_STAGE 98304           // Ah 16K | Al 16K | Bh 32K | Bl 32K
#define G1_DYN   (2 * G1_STAGE + 1024)
#define G1_IDESC ((1u << 4) | (32u << 17) | (8u << 24))    // F32 acc, f16 a/b, N=256, M=128

__global__ __launch_bounds__(256, 1)
void gemm1_k() {
#if HAS_TC05
    extern __shared__ char dyn[];
    __shared__ __align__(16) uint64_t s_mbar[2];
    __shared__ uint32_t s_tmem[1];

    const uint32_t raw = smem_u32(dyn);
    const uint32_t dbase = (raw + 1023u) & ~1023u;

    const int tid = threadIdx.x;
    const int wid = tid >> 5;
    const int lid = tid & 31;
    const int b   = blockIdx.z;
    const int mt  = blockIdx.y;
    const int nt  = blockIdx.x;
    const size_t bo = (size_t)b * SDIM * SDIM;
    const __half* Ah_g = g_Qh16 + bo + (size_t)mt * 128 * SDIM;
    const __half* Al_g = g_Ql16 + bo + (size_t)mt * 128 * SDIM;
    const __half* Bh_g = g_Kh16 + bo + (size_t)nt * 256 * SDIM;
    const __half* Bl_g = g_Kl16 + bo + (size_t)nt * 256 * SDIM;

    const uint32_t mb0 = smem_u32(&s_mbar[0]);
    const uint32_t mb1 = mb0 + 8;

    if (wid == 0) {
        asm volatile("tcgen05.alloc.cta_group::1.sync.aligned.shared::cta.b32 [%0], %1;"
                     :: "r"(smem_u32(s_tmem)), "r"(512u) : "memory");
    }
    if (tid == 0) { mbar_init(mb0, 1); mbar_init(mb1, 1); }
    __syncthreads();
    const uint32_t tmem = s_tmem[0];

    // Per-thread chunk maps (16B chunks, SW128 rows of 128B = 64 f16).
    uint32_t soffA[4], goffA[4], soffB[8], goffB[8];
    #pragma unroll
    for (int j = 0; j < 4; j++) {
        int i = tid + j * 256;              // 0..1023 : 128 rows x 8 chunks
        soffA[j] = swz(((uint32_t)(i >> 3) << 7) | ((uint32_t)(i & 7) << 4));
        goffA[j] = (uint32_t)(i >> 3) * SDIM + (uint32_t)(i & 7) * 8;
    }
    #pragma unroll
    for (int j = 0; j < 8; j++) {
        int i = tid + j * 256;              // 0..2047 : 256 rows x 8 chunks
        soffB[j] = swz(((uint32_t)(i >> 3) << 7) | ((uint32_t)(i & 7) << 4));
        goffB[j] = (uint32_t)(i >> 3) * SDIM + (uint32_t)(i & 7) * 8;
    }

    // Prologue: fill both stages.
    #pragma unroll
    for (int p = 0; p < 2; p++) {
        const uint32_t sb = dbase + p * G1_STAGE;
        const uint32_t ko = p * 64;
        #pragma unroll
        for (int j = 0; j < 4; j++) {
            cp16(sb +         soffA[j], Ah_g + goffA[j] + ko);
            cp16(sb + 16384 + soffA[j], Al_g + goffA[j] + ko);
        }
        #pragma unroll
        for (int j = 0; j < 8; j++) {
            cp16(sb + 32768 + soffB[j], Bh_g + goffB[j] + ko);
            cp16(sb + 65536 + soffB[j], Bl_g + goffB[j] + ko);
        }
        cp_commit();
    }

    uint32_t ph[2] = {0, 0};

    for (int kt = 0; kt < G1_NKT; kt++) {
        const int s = kt & 1;
        const uint32_t sb = dbase + s * G1_STAGE;

        if (kt == G1_NKT - 1) asm volatile("cp.async.wait_group 0;" ::: "memory");
        else                  asm volatile("cp.async.wait_group 1;" ::: "memory");
        asm volatile("fence.proxy.async.shared::cta;" ::: "memory");
        __syncthreads();

        if (wid == 0 && elect_one()) {
            const uint64_t dAh = make_desc_sw128(sb);
            const uint64_t dAl = make_desc_sw128(sb + 16384);
            const uint64_t dBh = make_desc_sw128(sb + 32768);
            const uint64_t dBl = make_desc_sw128(sb + 65536);
            #pragma unroll
            for (int ks = 0; ks < 4; ks++) {       // 16 f16 per k-step = 32B = +2 desc units
                const uint64_t o = (uint64_t)(ks * 2);
                const uint32_t en = (kt > 0 || ks > 0) ? 1u : 0u;
                mma_f16_ss(tmem,       dAh + o, dBh + o, G1_IDESC, en);
                mma_f16_ss(tmem + 256, dAh + o, dBl + o, G1_IDESC, en);
                mma_f16_ss(tmem + 256, dAl + o, dBh + o, G1_IDESC, 1u);
            }
            tc_commit(s == 0 ? mb0 : mb1);
        }

        if (kt + 2 < G1_NKT) {                    // refill this stage
            mbar_wait(s == 0 ? mb0 : mb1, ph[s]);
            ph[s] ^= 1;
            const uint32_t ko = (uint32_t)(kt + 2) * 64;
            #pragma unroll
            for (int j = 0; j < 4; j++) {
                cp16(sb +         soffA[j], Ah_g + goffA[j] + ko);
                cp16(sb + 16384 + soffA[j], Al_g + goffA[j] + ko);
            }
            #pragma unroll
            for (int j = 0; j < 8; j++) {
                cp16(sb + 32768 + soffB[j], Bh_g + goffB[j] + ko);
                cp16(sb + 65536 + soffB[j], Bl_g + goffB[j] + ko);
            }
            cp_commit();
        }
    }

    mbar_wait(mb0, ph[0]);
    mbar_wait(mb1, ph[1]);
    asm volatile("tcgen05.fence::after_thread_sync;" ::: "memory");

    // Epilogue: warp w -> rows (w&3)*32+lid, cols (w>>2)*128 .. +127.
    {
        const int sub  = wid & 3;
        const int half = wid >> 2;
        const int row  = sub * 32 + lid;
        float* Cb = g_P + bo + ((size_t)mt * 128 + row) * SDIM
                         + (size_t)nt * 256 + (size_t)half * 128;
        const float inv = 1.0f / 4096.0f;
        #pragma unroll
        for (int c0 = 0; c0 < 128; c0 += 32) {
            uint32_t rh[32], rx[32];
            tmem_ld32(rh, tmem + (uint32_t)(half * 128 + c0));
            tmem_ld32(rx, tmem + (uint32_t)(256 + half * 128 + c0));
            #pragma unroll
            for (int j = 0; j < 8; j++) {
                float4 v;
                v.x = __uint_as_float(rh[4*j+0]) + __uint_as_float(rx[4*j+0]) * inv;
                v.y = __uint_as_float(rh[4*j+1]) + __uint_as_float(rx[4*j+1]) * inv;
                v.z = __uint_as_float(rh[4*j+2]) + __uint_as_float(rx[4*j+2]) * inv;
                v.w = __uint_as_float(rh[4*j+3]) + __uint_as_float(rx[4*j+3]) * inv;
                *(float4*)(Cb + c0 + 4*j) = v;
            }
        }
    }

    __syncthreads();
    if (tid == 0) { mbar_inval(mb0); mbar_inval(mb1); }
    __syncthreads();
    if (wid == 0) {
        asm volatile("tcgen05.relinquish_alloc_permit.cta_group::1.sync.aligned;");
        asm volatile("tcgen05.dealloc.cta_group::1.sync.aligned.b32 %0, %1;"
                     :: "r"(tmem), "r"(512u));
    }
#endif
}

// ===========================================================================
// Pass 2: softmax over last dim, in place on g_P.
// ===========================================================================
__global__ __launch_bounds__(256)
void softmax_rows() {
    __shared__ float red[8];
    float* p = g_P + (size_t)blockIdx.x * SDIM;
    const int tid  = threadIdx.x;
    const int lane = tid & 31;
    const int warp = tid >> 5;

    float4 a = *(const float4*)(p + tid * 4);
    float4 b = *(const float4*)(p + 1024 + tid * 4);

    float m = fmaxf(fmaxf(fmaxf(a.x, a.y), fmaxf(a.z, a.w)),
                    fmaxf(fmaxf(b.x, b.y), fmaxf(b.z, b.w)));
    #pragma unroll
    for (int o = 16; o > 0; o >>= 1)
        m = fmaxf(m, __shfl_xor_sync(0xffffffffu, m, o));
    if (lane == 0) red[warp] = m;
    __syncthreads();
    m = red[0];
    #pragma unroll
    for (int i = 1; i < 8; i++) m = fmaxf(m, red[i]);
    __syncthreads();

    a.x = expf(a.x - m); a.y = expf(a.y - m); a.z = expf(a.z - m); a.w = expf(a.w - m);
    b.x = expf(b.x - m); b.y = expf(b.y - m); b.z = expf(b.z - m); b.w = expf(b.w - m);

    float s = (a.x + a.y) + (a.z + a.w) + (b.x + b.y) + (b.z + b.w);
    #pragma unroll
    for (int o = 16; o > 0; o >>= 1)
        s += __shfl_xor_sync(0xffffffffu, s, o);
    if (lane == 0) red[warp] = s;
    __syncthreads();
    s = red[0] + red[1] + red[2] + red[3] + red[4] + red[5] + red[6] + red[7];

    const float r = 1.0f / s;
    a.x *= r; a.y *= r; a.z *= r; a.w *= r;
    b.x *= r; b.y *= r; b.z *= r; b.w *= r;
    *(float4*)(p + tid * 4)        = a;
    *(float4*)(p + 1024 + tid * 4) = b;
}

// ===========================================================================
// Pass 3: Pt[b][k][d] = tf32(P[b][d][k])  (32x32 smem tile transpose)
// ===========================================================================
__global__ __launch_bounds__(256)
void transpose_p() {
    __shared__ float t[32][33];
    const int b  = blockIdx.z;
    const int d0 = blockIdx.y * 32;
    const int k0 = blockIdx.x * 32;
    const int x  = threadIdx.x;        // 0..31
    const int y  = threadIdx.y;        // 0..7
    const size_t bo = (size_t)b * SDIM * SDIM;

    #pragma unroll
    for (int j = 0; j < 4; j++)
        t[y + 8*j][x] = g_P[bo + (size_t)(d0 + y + 8*j) * SDIM + k0 + x];
    __syncthreads();
    #pragma unroll
    for (int j = 0; j < 4; j++)
        g_Pt[bo + (size_t)(k0 + y + 8*j) * SDIM + d0 + x] = to_tf32(t[x][y + 8*j]);
}

// ===========================================================================
// Pass 4: out = V @ P (NT vs Pt) via tcgen05 tf32. CTA 128x256, BK=32 fp32.
// ===========================================================================
#define G2_NKT   64
#define G2_STAGE 49152           // A 16K | B 32K
#define G2_DYN   (3 * G2_STAGE + 1024)
#define G2_IDESC ((1u << 4) | (2u << 7) | (2u << 10) | (32u << 17) | (8u << 24))

__global__ __launch_bounds__(256, 1)
void gemm2_k(const float* __restrict__ V, float* __restrict__ O) {
#if HAS_TC05
    extern __shared__ char dyn[];
    __shared__ __align__(16) uint64_t s_mbar[3];
    __shared__ uint32_t s_tmem[1];

    const uint32_t raw = smem_u32(dyn);
    const uint32_t dbase = (raw + 1023u) & ~1023u;

    const int tid = threadIdx.x;
    const int wid = tid >> 5;
    const int lid = tid & 31;
    const int b   = blockIdx.z;
    const int mt  = blockIdx.y;
    const int nt  = blockIdx.x;
    const size_t bo = (size_t)b * SDIM * SDIM;
    const float* Ag = V    + bo + (size_t)mt * 128 * SDIM;
    const float* Bg = g_Pt + bo + (size_t)nt * 256 * SDIM;

    const uint32_t mbb = smem_u32(&s_mbar[0]);

    if (wid == 0) {
        asm volatile("tcgen05.alloc.cta_group::1.sync.aligned.shared::cta.b32 [%0], %1;"
                     :: "r"(smem_u32(s_tmem)), "r"(256u) : "memory");
    }
    if (tid == 0) { mbar_init(mbb, 1); mbar_init(mbb + 8, 1); mbar_init(mbb + 16, 1); }
    __syncthreads();
    const uint32_t tmem = s_tmem[0];

    // Chunk maps: fp32 rows of 32 floats = 128B = 8 x 16B chunks.
    uint32_t soffA[4], goffA[4], soffB[8], goffB[8];
    #pragma unroll
    for (int j = 0; j < 4; j++) {
        int i = tid + j * 256;              // 128 rows x 8 chunks
        soffA[j] = swz(((uint32_t)(i >> 3) << 7) | ((uint32_t)(i & 7) << 4));
        goffA[j] = (uint32_t)(i >> 3) * SDIM + (uint32_t)(i & 7) * 4;
    }
    #pragma unroll
    for (int j = 0; j < 8; j++) {
        int i = tid + j * 256;              // 256 rows x 8 chunks
        soffB[j] = swz(((uint32_t)(i >> 3) << 7) | ((uint32_t)(i & 7) << 4));
        goffB[j] = (uint32_t)(i >> 3) * SDIM + (uint32_t)(i & 7) * 4;
    }

    #pragma unroll
    for (int p = 0; p < 3; p++) {
        const uint32_t sb = dbase + p * G2_STAGE;
        const uint32_t ko = p * 32;
        #pragma unroll
        for (int j = 0; j < 4; j++) cp16(sb +         soffA[j], Ag + goffA[j] + ko);
        #pragma unroll
        for (int j = 0; j < 8; j++) cp16(sb + 16384 + soffB[j], Bg + goffB[j] + ko);
        cp_commit();
    }

    uint32_t ph[3] = {0, 0, 0};
    int s = 0;

    for (int kt = 0; kt < G2_NKT; kt++) {
        const uint32_t sb = dbase + s * G2_STAGE;

        if      (kt >= G2_NKT - 1) asm volatile("cp.async.wait_group 0;" ::: "memory");
        else if (kt == G2_NKT - 2) asm volatile("cp.async.wait_group 1;" ::: "memory");
        else                       asm volatile("cp.async.wait_group 2;" ::: "memory");
        asm volatile("fence.proxy.async.shared::cta;" ::: "memory");
        __syncthreads();

        if (wid == 0 && elect_one()) {
            const uint64_t dA = make_desc_sw128(sb);
            const uint64_t dB = make_desc_sw128(sb + 16384);
            #pragma unroll
            for (int ks = 0; ks < 4; ks++) {   // 8 tf32 per k-step = 32B = +2 units
                const uint64_t o = (uint64_t)(ks * 2);
                mma_tf32_ss(tmem, dA + o, dB + o, G2_IDESC, (kt > 0 || ks > 0) ? 1u : 0u);
            }
            tc_commit(mbb + 8 * s);
        }

        if (kt + 3 < G2_NKT) {
            mbar_wait(mbb + 8 * s, ph[s]);
            ph[s] ^= 1;
            const uint32_t ko = (uint32_t)(kt + 3) * 32;
            #pragma unroll
            for (int j = 0; j < 4; j++) cp16(sb +         soffA[j], Ag + goffA[j] + ko);
            #pragma unroll
            for (int j = 0; j < 8; j++) cp16(sb + 16384 + soffB[j], Bg + goffB[j] + ko);
            cp_commit();
        }
        s = (s == 2) ? 0 : s + 1;
    }

    mbar_wait(mbb,      ph[0]);
    mbar_wait(mbb + 8,  ph[1]);
    mbar_wait(mbb + 16, ph[2]);
    asm volatile("tcgen05.fence::after_thread_sync;" ::: "memory");

    {
        const int sub  = wid & 3;
        const int half = wid >> 2;
        const int row  = sub * 32 + lid;
        float* Ob = O + bo + ((size_t)mt * 128 + row) * SDIM
                       + (size_t)nt * 256 + (size_t)half * 128;
        #pragma unroll
        for (int c0 = 0; c0 < 128; c0 += 32) {
            uint32_t r[32];
            tmem_ld32(r, tmem + (uint32_t)(half * 128 + c0));
            #pragma unroll
            for (int j = 0; j < 8; j++) {
                float4 v;
                v.x = __uint_as_float(r[4*j+0]);
                v.y = __uint_as_float(r[4*j+1]);
                v.z = __uint_as_float(r[4*j+2]);
                v.w = __uint_as_float(r[4*j+3]);
                *(float4*)(Ob + c0 + 4*j) = v;
            }
        }
    }

    __syncthreads();
    if (tid == 0) { mbar_inval(mbb); mbar_inval(mbb + 8); mbar_inval(mbb + 16); }
    __syncthreads();
    if (wid == 0) {
        asm volatile("tcgen05.relinquish_alloc_permit.cta_group::1.sync.aligned;");
        asm volatile("tcgen05.dealloc.cta_group::1.sync.aligned.b32 %0, %1;"
                     :: "r"(tmem), "r"(256u));
    }
#endif
}

// ===========================================================================
extern "C" void kernel_launch(void* const* d_in, const int* in_sizes, int n_in,
                              void* d_out, int out_size) {
    (void)in_sizes; (void)n_in; (void)out_size;
    const float* Q = (const float*)d_in[0];
    const float* K = (const float*)d_in[1];
    const float* V = (const float*)d_in[2];
    float* O = (float*)d_out;

    cudaFuncSetAttribute((const void*)gemm1_k,
                         cudaFuncAttributeMaxDynamicSharedMemorySize, G1_DYN);
    cudaFuncSetAttribute((const void*)gemm2_k,
                         cudaFuncAttributeMaxDynamicSharedMemorySize, G2_DYN);

    split16<<<(unsigned)(NELEM / 4 / 256), 256>>>(Q, K);
    gemm1_k<<<dim3(SDIM / 256, SDIM / 128, BATCH), 256, G1_DYN>>>();
    softmax_rows<<<BATCH * SDIM, 256>>>();
    transpose_p<<<dim3(SDIM / 32, SDIM / 32, BATCH), dim3(32, 8)>>>();
    gemm2_k<<<dim3(SDIM / 256, SDIM / 128, BATCH), 256, G2_DYN>>>(V, O);
}